// round 5
// baseline (speedup 1.0000x reference)
#include <cuda_runtime.h>
#include <math.h>

// Problem constants
#define FEAT 384
#define FFN  768
#define ZDIM 384
#define HID  192
#define BB   4
#define NN_  128
#define ROWS (BB*NN_)   // 512

typedef unsigned long long ull;

// ---------------- scratch (device globals; no allocation allowed) ----------------
__device__ float g_xh[ROWS*ZDIM];     // first half of gelu(x@U_w+U_b)
__device__ float g_z [ROWS*ZDIM];     // second half, then LayerNormed in-place
__device__ float g_henc[ROWS*HID];    // gelu(z@enc_w+enc_b)
__device__ float g_w   [ROWS*HID];    // z @ dec_w^T
__device__ float g_XV  [ROWS*FEAT];   // xh @ V_w
__device__ float g_c0  [ZDIM];        // AE(0) = gelu(enc_b)@dec_w + dec_b
__device__ float g_d0  [ROWS];        // c0 . z_ln
__device__ float g_d1b [ROWS];        // dec_b . z_ln
__device__ float g_alpha[ROWS];
__device__ float g_beta [ROWS];
__device__ float g_TV  [BB*FEAT];     // per-batch T @ V_w

// ---------------- helpers ----------------
__device__ __forceinline__ float gelu_f(float x) {
    return 0.5f * x * (1.0f + erff(x * 0.70710678118654752440f));
}
__device__ __forceinline__ ull pack2(float x, float y) {
    ull r; asm("mov.b64 %0, {%1,%2};" : "=l"(r) : "f"(x), "f"(y)); return r;
}
__device__ __forceinline__ void fma2(ull &acc, ull a, ull b) {
    asm("fma.rn.f32x2 %0, %1, %2, %0;" : "+l"(acc) : "l"(a), "l"(b));
}
__device__ __forceinline__ float2 unpack2(ull v) {
    float2 f; asm("mov.b64 {%0,%1}, %2;" : "=f"(f.x), "=f"(f.y) : "l"(v)); return f;
}

// ---------------- K0: c0 = gelu(enc_b) @ dec_w + dec_b  (1 block, 384 thr) ----------------
__global__ void k0_c0(const float* __restrict__ enc_b,
                      const float* __restrict__ dec_w,
                      const float* __restrict__ dec_b) {
    __shared__ float sg[HID];
    int t = threadIdx.x;
    if (t < HID) sg[t] = gelu_f(enc_b[t]);
    __syncthreads();
    float acc = dec_b[t];
    #pragma unroll 4
    for (int h = 0; h < HID; h++) acc += sg[h] * dec_w[h*ZDIM + t];
    g_c0[t] = acc;
}

// ---------------- K1: h = gelu(x @ U_w + U_b), split -> g_xh | g_z ----------------
// Tiled 64x64x16, 256 threads, packed f32x2 accumulation along M pairs.
__global__ __launch_bounds__(256) void k1_gemm(const float* __restrict__ A,
                                               const float* __restrict__ Bw,
                                               const float* __restrict__ bias) {
    __shared__ __align__(16) float As[16][66];
    __shared__ __align__(16) float Bs[16][68];
    const int m0 = blockIdx.y * 64, n0 = blockIdx.x * 64;
    const int t  = threadIdx.x;
    const int tx = t & 15, ty = t >> 4;
    const int mb = ty * 4, nb = tx * 4;
    ull acc[2][4];
    #pragma unroll
    for (int p = 0; p < 2; p++)
        #pragma unroll
        for (int n = 0; n < 4; n++) acc[p][n] = 0ULL;

    const int lm  = t >> 2,  lk = (t & 3) << 2;   // A tile load mapping
    const int lkb = t >> 4,  ln = (t & 15) << 2;  // B tile load mapping

    for (int k0 = 0; k0 < FEAT; k0 += 16) {
        float4 av = *(const float4*)(A + (m0 + lm) * FEAT + k0 + lk);
        As[lk+0][lm] = av.x; As[lk+1][lm] = av.y;
        As[lk+2][lm] = av.z; As[lk+3][lm] = av.w;
        float4 bv = *(const float4*)(Bw + (k0 + lkb) * FFN + n0 + ln);
        *(float4*)&Bs[lkb][ln] = bv;
        __syncthreads();
        #pragma unroll
        for (int kk = 0; kk < 16; kk++) {
            ull a0 = *(const ull*)&As[kk][mb];
            ull a1 = *(const ull*)&As[kk][mb+2];
            #pragma unroll
            for (int n = 0; n < 4; n++) {
                float b = Bs[kk][nb + n];
                ull bb = pack2(b, b);
                fma2(acc[0][n], a0, bb);
                fma2(acc[1][n], a1, bb);
            }
        }
        __syncthreads();
    }
    #pragma unroll
    for (int p = 0; p < 2; p++) {
        #pragma unroll
        for (int n = 0; n < 4; n++) {
            float2 v = unpack2(acc[p][n]);
            int col = n0 + nb + n;
            float bc = bias[col];
            float y0 = gelu_f(v.x + bc);
            float y1 = gelu_f(v.y + bc);
            int m = m0 + mb + 2*p;
            if (col < ZDIM) {
                g_xh[m*ZDIM + col]     = y0;
                g_xh[(m+1)*ZDIM + col] = y1;
            } else {
                int c = col - ZDIM;
                g_z[m*ZDIM + c]     = y0;
                g_z[(m+1)*ZDIM + c] = y1;
            }
        }
    }
}

// ---------------- K2: LayerNorm rows of g_z (in place) + d0, d1b dots ----------------
__global__ __launch_bounds__(128) void k2_ln(const float* __restrict__ ln_w,
                                             const float* __restrict__ ln_b,
                                             const float* __restrict__ dec_b) {
    const int row = blockIdx.x;
    const int t = threadIdx.x;
    __shared__ float red[128];
    float v[3];
    #pragma unroll
    for (int i = 0; i < 3; i++) v[i] = g_z[row*ZDIM + t + i*128];

    float s = v[0] + v[1] + v[2];
    red[t] = s; __syncthreads();
    for (int st = 64; st > 0; st >>= 1) { if (t < st) red[t] += red[t+st]; __syncthreads(); }
    float mu = red[0] * (1.0f/384.0f);
    __syncthreads();

    float sq = 0.f;
    #pragma unroll
    for (int i = 0; i < 3; i++) { float d = v[i] - mu; sq += d*d; }
    red[t] = sq; __syncthreads();
    for (int st = 64; st > 0; st >>= 1) { if (t < st) red[t] += red[t+st]; __syncthreads(); }
    float var = red[0] * (1.0f/384.0f);
    float rs = rsqrtf(var + 1e-5f);
    __syncthreads();

    float pd0 = 0.f, pd1 = 0.f;
    #pragma unroll
    for (int i = 0; i < 3; i++) {
        int f = t + i*128;
        float zn = (v[i] - mu) * rs * ln_w[f] + ln_b[f];
        g_z[row*ZDIM + f] = zn;
        pd0 += g_c0[f] * zn;
        pd1 += dec_b[f] * zn;
    }
    red[t] = pd0; __syncthreads();
    for (int st = 64; st > 0; st >>= 1) { if (t < st) red[t] += red[t+st]; __syncthreads(); }
    if (t == 0) g_d0[row] = red[0];
    __syncthreads();
    red[t] = pd1; __syncthreads();
    for (int st = 64; st > 0; st >>= 1) { if (t < st) red[t] += red[t+st]; __syncthreads(); }
    if (t == 0) g_d1b[row] = red[0];
}

// ---------------- K3: three GEMMs in one launch (blockIdx.z selects) ----------------
// op0: henc = gelu(z@enc_w + enc_b)  [512x192, NN]
// op1: w    = z @ dec_w^T            [512x192, NT]
// op2: XV   = xh @ V_w               [512x384, NN]
__global__ __launch_bounds__(256) void k3_gemm(const float* __restrict__ enc_w,
                                               const float* __restrict__ enc_b,
                                               const float* __restrict__ dec_w,
                                               const float* __restrict__ V_w) {
    const int op = blockIdx.z;
    if (op < 2 && blockIdx.x >= 3) return;   // henc/w only 192 cols wide

    __shared__ __align__(16) float As[16][66];
    __shared__ __align__(16) float Bs[16][68];
    const int m0 = blockIdx.y * 64, n0 = blockIdx.x * 64;
    const int t  = threadIdx.x;
    const int tx = t & 15, ty = t >> 4;
    const int mb = ty * 4, nb = tx * 4;
    const float* A = (op == 2) ? g_xh : g_z;

    ull acc[2][4];
    #pragma unroll
    for (int p = 0; p < 2; p++)
        #pragma unroll
        for (int n = 0; n < 4; n++) acc[p][n] = 0ULL;

    const int lm  = t >> 2,  lk = (t & 3) << 2;
    const int lkb = t >> 4,  ln = (t & 15) << 2;
    const int lnt = t >> 2,  lkq = (t & 3) << 2;  // NT mapping

    for (int k0 = 0; k0 < ZDIM; k0 += 16) {
        float4 av = *(const float4*)(A + (m0 + lm) * ZDIM + k0 + lk);
        As[lk+0][lm] = av.x; As[lk+1][lm] = av.y;
        As[lk+2][lm] = av.z; As[lk+3][lm] = av.w;
        if (op == 0) {
            float4 bv = *(const float4*)(enc_w + (k0 + lkb) * HID + n0 + ln);
            *(float4*)&Bs[lkb][ln] = bv;
        } else if (op == 2) {
            float4 bv = *(const float4*)(V_w + (k0 + lkb) * FEAT + n0 + ln);
            *(float4*)&Bs[lkb][ln] = bv;
        } else { // NT: Bs[kk][n] = dec_w[(n0+n)*ZDIM + k0+kk]
            float4 bv = *(const float4*)(dec_w + (n0 + lnt) * ZDIM + k0 + lkq);
            Bs[lkq+0][lnt] = bv.x; Bs[lkq+1][lnt] = bv.y;
            Bs[lkq+2][lnt] = bv.z; Bs[lkq+3][lnt] = bv.w;
        }
        __syncthreads();
        #pragma unroll
        for (int kk = 0; kk < 16; kk++) {
            ull a0 = *(const ull*)&As[kk][mb];
            ull a1 = *(const ull*)&As[kk][mb+2];
            #pragma unroll
            for (int n = 0; n < 4; n++) {
                float b = Bs[kk][nb + n];
                ull bb = pack2(b, b);
                fma2(acc[0][n], a0, bb);
                fma2(acc[1][n], a1, bb);
            }
        }
        __syncthreads();
    }
    #pragma unroll
    for (int p = 0; p < 2; p++) {
        #pragma unroll
        for (int n = 0; n < 4; n++) {
            float2 v = unpack2(acc[p][n]);
            int col = n0 + nb + n;
            int m = m0 + mb + 2*p;
            if (op == 0) {
                float bc = enc_b[col];
                g_henc[m*HID + col]     = gelu_f(v.x + bc);
                g_henc[(m+1)*HID + col] = gelu_f(v.y + bc);
            } else if (op == 1) {
                g_w[m*HID + col]     = v.x;
                g_w[(m+1)*HID + col] = v.y;
            } else {
                g_XV[m*FEAT + col]     = v.x;
                g_XV[(m+1)*FEAT + col] = v.y;
            }
        }
    }
}

// ---------------- K4: per batch — d1, softmax collapse, T, TV = T@V_w ----------------
__global__ __launch_bounds__(384) void k4_batch(const float* __restrict__ V_w) {
    const int b = blockIdx.x;
    const int t = threadIdx.x;
    __shared__ float sd0[128], sd1[128], sE0[128], red[128], sT[384];

    if (t < 128) sd0[t] = g_d0[b*128 + t];

    // d1[i] = henc[i].w[i] + d1b[i]  — one warp per row stripe
    const int wid = t >> 5, lane = t & 31;
    for (int i = wid; i < 128; i += 12) {
        int g = b*128 + i;
        float acc = 0.f;
        #pragma unroll
        for (int j = 0; j < 6; j++) {
            int h = lane + j*32;
            acc += g_henc[g*HID + h] * g_w[g*HID + h];
        }
        #pragma unroll
        for (int o = 16; o; o >>= 1) acc += __shfl_xor_sync(0xffffffffu, acc, o);
        if (lane == 0) sd1[i] = acc + g_d1b[g];
    }
    __syncthreads();

    // global max
    if (t < 128) red[t] = fmaxf(sd0[t], sd1[t]);
    __syncthreads();
    for (int st = 64; st > 0; st >>= 1) { if (t < st) red[t] = fmaxf(red[t], red[t+st]); __syncthreads(); }
    float M = red[0];
    __syncthreads();

    float e0 = 0.f, e1 = 0.f;
    if (t < 128) {
        e0 = expf(sd0[t] - M);
        e1 = expf(sd1[t] - M);
        sE0[t] = e0;
        red[t] = e0;
    }
    __syncthreads();
    for (int st = 64; st > 0; st >>= 1) { if (t < st) red[t] += red[t+st]; __syncthreads(); }
    float Ssum = red[0];

    if (t < 128) {
        float S = Ssum - e0 + e1;
        float a = 1.0f / S;
        g_alpha[b*128 + t] = a;
        g_beta [b*128 + t] = (e1 - e0) * a;
    }

    // T[f] = sum_j E0[j] * xh[b,j,f]
    float acc = 0.f;
    #pragma unroll 4
    for (int j = 0; j < 128; j++) acc += sE0[j] * g_xh[(b*128 + j)*ZDIM + t];
    sT[t] = acc;
    __syncthreads();

    // TV[b,f] = T @ V_w
    float acc2 = 0.f;
    #pragma unroll 4
    for (int k = 0; k < ZDIM; k++) acc2 += sT[k] * V_w[k*FEAT + t];
    g_TV[b*FEAT + t] = acc2;
}

// ---------------- K5: y = alpha*TV + beta*XV + V_b ----------------
__global__ __launch_bounds__(384) void k5_out(const float* __restrict__ V_b,
                                              float* __restrict__ out) {
    const int m = blockIdx.x;           // 0..511
    const int t = threadIdx.x;          // 0..383
    const int b = m >> 7;
    out[m*FEAT + t] = g_alpha[m] * g_TV[b*FEAT + t]
                    + g_beta[m]  * g_XV[m*FEAT + t]
                    + V_b[t];
}

// ---------------- launch ----------------
extern "C" void kernel_launch(void* const* d_in, const int* in_sizes, int n_in,
                              void* d_out, int out_size) {
    const float* x     = (const float*)d_in[0];
    const float* U_w   = (const float*)d_in[1];
    const float* U_b   = (const float*)d_in[2];
    const float* ln_w  = (const float*)d_in[3];
    const float* ln_b  = (const float*)d_in[4];
    const float* enc_w = (const float*)d_in[5];
    const float* enc_b = (const float*)d_in[6];
    const float* dec_w = (const float*)d_in[7];
    const float* dec_b = (const float*)d_in[8];
    const float* V_w   = (const float*)d_in[9];
    const float* V_b   = (const float*)d_in[10];
    float* out = (float*)d_out;

    k0_c0<<<1, 384>>>(enc_b, dec_w, dec_b);
    k1_gemm<<<dim3(FFN/64, ROWS/64), 256>>>(x, U_w, U_b);
    k2_ln<<<ROWS, 128>>>(ln_w, ln_b, dec_b);
    k3_gemm<<<dim3(FEAT/64, ROWS/64, 3), 256>>>(enc_w, enc_b, dec_w, V_w);
    k4_batch<<<BB, 384>>>(V_w);
    k5_out<<<ROWS, 384>>>(V_b, out);
}

// round 8
// speedup vs baseline: 1.0658x; 1.0658x over previous
#include <cuda_runtime.h>
#include <math.h>

// Problem constants
#define FEAT 384
#define FFN  768
#define ZDIM 384
#define HID  192
#define BB   4
#define ROWS 512

// GEMM tiling
#define BM 32
#define BN 32
#define BK 32
#define TPB 128

typedef unsigned long long ull;

// ---------------- scratch ----------------
__device__ __align__(16) float g_xh[ROWS*ZDIM];
__device__ __align__(16) float g_z [ROWS*ZDIM];
__device__ __align__(16) float g_henc[ROWS*HID];
__device__ __align__(16) float g_w   [ROWS*HID];
__device__ __align__(16) float g_XV  [ROWS*FEAT];
__device__ __align__(16) float g_c0  [ZDIM];
__device__ float g_d0  [ROWS];
__device__ float g_d1b [ROWS];
__device__ float g_alpha[ROWS];
__device__ float g_beta [ROWS];
__device__ __align__(16) float g_T [BB*ZDIM];
__device__ __align__(16) float g_TV[BB*FEAT];

// ---------------- helpers ----------------
__device__ __forceinline__ float gelu_f(float x) {
    return 0.5f * x * (1.0f + erff(x * 0.70710678118654752440f));
}
__device__ __forceinline__ void fma2(ull &acc, ull a, ull b) {
    asm("fma.rn.f32x2 %0, %1, %2, %0;" : "+l"(acc) : "l"(a), "l"(b));
}
__device__ __forceinline__ float2 unpack2(ull v) {
    float2 f; asm("mov.b64 {%0,%1}, %2;" : "=f"(f.x), "=f"(f.y) : "l"(v)); return f;
}

// ---------------- K0: c0 = gelu(enc_b) @ dec_w + dec_b ----------------
__global__ void k0_c0(const float* __restrict__ enc_b,
                      const float* __restrict__ dec_w,
                      const float* __restrict__ dec_b) {
    __shared__ float sg[HID];
    int t = threadIdx.x;
    if (t < HID) sg[t] = gelu_f(enc_b[t]);
    __syncthreads();
    float acc = dec_b[t];
    #pragma unroll 4
    for (int h = 0; h < HID; h++) acc += sg[h] * dec_w[h*ZDIM + t];
    g_c0[t] = acc;
}

// ---------------- K1: h = gelu(x @ U_w + U_b) split -> g_xh | g_z ----------------
// 32x32x32 double-buffered, 128 threads, B duplicated in smem for f32x2.
__global__ __launch_bounds__(TPB) void k1_gemm(const float* __restrict__ A,
                                               const float* __restrict__ Bw,
                                               const float* __restrict__ bias) {
    __shared__ __align__(16) float As[2][BK][BM+4];
    __shared__ __align__(16) float Bs[2][BK][2*BN+4];
    const int bid = blockIdx.x;
    const int n0 = (bid % 24) * BN;
    const int m0 = (bid / 24) * BM;
    const int t  = threadIdx.x;
    const int tx = t & 15, ty = t >> 4;
    const int ar = t >> 3, ac = (t & 7) * 4;   // A loader: rows ar, ar+16 ; k-offset ac
    const int bk = t >> 3, bn = (t & 7) * 4;   // B loader: k rows bk, bk+16 ; col bn

    ull acc0=0, acc1=0, acc2=0, acc3=0;
    float4 a0v, a1v, b0v, b1v;

    const float* Ar0 = A + (m0+ar)*FEAT + ac;
    const float* Ar1 = A + (m0+ar+16)*FEAT + ac;
    const float* Br0 = Bw + bk*FFN + n0 + bn;
    const float* Br1 = Bw + (bk+16)*FFN + n0 + bn;

    a0v = *(const float4*)(Ar0);
    a1v = *(const float4*)(Ar1);
    b0v = *(const float4*)(Br0);
    b1v = *(const float4*)(Br1);
    #pragma unroll
    for (int j=0;j<4;j++){ As[0][ac+j][ar]=(&a0v.x)[j]; As[0][ac+j][ar+16]=(&a1v.x)[j]; }
    *(float4*)&Bs[0][bk   ][bn*2  ] = make_float4(b0v.x,b0v.x,b0v.y,b0v.y);
    *(float4*)&Bs[0][bk   ][bn*2+4] = make_float4(b0v.z,b0v.z,b0v.w,b0v.w);
    *(float4*)&Bs[0][bk+16][bn*2  ] = make_float4(b1v.x,b1v.x,b1v.y,b1v.y);
    *(float4*)&Bs[0][bk+16][bn*2+4] = make_float4(b1v.z,b1v.z,b1v.w,b1v.w);
    __syncthreads();

    int buf = 0;
    #pragma unroll 1
    for (int kt = 0; kt < FEAT/BK; kt++) {
        if (kt < FEAT/BK - 1) {
            const int k0 = (kt+1)*BK;
            a0v = *(const float4*)(Ar0 + k0);
            a1v = *(const float4*)(Ar1 + k0);
            b0v = *(const float4*)(Br0 + k0*FFN);
            b1v = *(const float4*)(Br1 + k0*FFN);
        }
        #pragma unroll
        for (int kk = 0; kk < BK; kk++) {
            ulonglong2 av = *(const ulonglong2*)&As[buf][kk][ty*4];
            ulonglong2 bv = *(const ulonglong2*)&Bs[buf][kk][tx*4];
            fma2(acc0, av.x, bv.x);
            fma2(acc1, av.x, bv.y);
            fma2(acc2, av.y, bv.x);
            fma2(acc3, av.y, bv.y);
        }
        if (kt < FEAT/BK - 1) {
            const int nb = buf ^ 1;
            #pragma unroll
            for (int j=0;j<4;j++){ As[nb][ac+j][ar]=(&a0v.x)[j]; As[nb][ac+j][ar+16]=(&a1v.x)[j]; }
            *(float4*)&Bs[nb][bk   ][bn*2  ] = make_float4(b0v.x,b0v.x,b0v.y,b0v.y);
            *(float4*)&Bs[nb][bk   ][bn*2+4] = make_float4(b0v.z,b0v.z,b0v.w,b0v.w);
            *(float4*)&Bs[nb][bk+16][bn*2  ] = make_float4(b1v.x,b1v.x,b1v.y,b1v.y);
            *(float4*)&Bs[nb][bk+16][bn*2+4] = make_float4(b1v.z,b1v.z,b1v.w,b1v.w);
        }
        __syncthreads();
        buf ^= 1;
    }

    // epilogue: gelu + bias, split store
    const int col = n0 + tx*2;
    const int r   = m0 + ty*4;
    float2 c0 = unpack2(acc0), c1 = unpack2(acc1), c2 = unpack2(acc2), c3 = unpack2(acc3);
    float bs0 = bias[col], bs1 = bias[col+1];
    float* dst; int cc;
    if (col < ZDIM) { dst = g_xh; cc = col; } else { dst = g_z; cc = col - ZDIM; }
    dst[(r+0)*ZDIM+cc  ] = gelu_f(c0.x + bs0);
    dst[(r+1)*ZDIM+cc  ] = gelu_f(c0.y + bs0);
    dst[(r+2)*ZDIM+cc  ] = gelu_f(c2.x + bs0);
    dst[(r+3)*ZDIM+cc  ] = gelu_f(c2.y + bs0);
    dst[(r+0)*ZDIM+cc+1] = gelu_f(c1.x + bs1);
    dst[(r+1)*ZDIM+cc+1] = gelu_f(c1.y + bs1);
    dst[(r+2)*ZDIM+cc+1] = gelu_f(c3.x + bs1);
    dst[(r+3)*ZDIM+cc+1] = gelu_f(c3.y + bs1);
}

// ---------------- K2: LayerNorm rows of g_z (in place) + d0, d1b dots ----------------
__global__ __launch_bounds__(128) void k2_ln(const float* __restrict__ ln_w,
                                             const float* __restrict__ ln_b,
                                             const float* __restrict__ dec_b) {
    const int row = blockIdx.x;
    const int t = threadIdx.x;
    __shared__ float red[128];
    float v[3];
    #pragma unroll
    for (int i = 0; i < 3; i++) v[i] = g_z[row*ZDIM + t + i*128];

    float s = v[0] + v[1] + v[2];
    red[t] = s; __syncthreads();
    for (int st = 64; st > 0; st >>= 1) { if (t < st) red[t] += red[t+st]; __syncthreads(); }
    float mu = red[0] * (1.0f/384.0f);
    __syncthreads();

    float sq = 0.f;
    #pragma unroll
    for (int i = 0; i < 3; i++) { float d = v[i] - mu; sq += d*d; }
    red[t] = sq; __syncthreads();
    for (int st = 64; st > 0; st >>= 1) { if (t < st) red[t] += red[t+st]; __syncthreads(); }
    float var = red[0] * (1.0f/384.0f);
    float rs = rsqrtf(var + 1e-5f);
    __syncthreads();

    float pd0 = 0.f, pd1 = 0.f;
    #pragma unroll
    for (int i = 0; i < 3; i++) {
        int f = t + i*128;
        float zn = (v[i] - mu) * rs * ln_w[f] + ln_b[f];
        g_z[row*ZDIM + f] = zn;
        pd0 += g_c0[f] * zn;
        pd1 += dec_b[f] * zn;
    }
    red[t] = pd0; __syncthreads();
    for (int st = 64; st > 0; st >>= 1) { if (t < st) red[t] += red[t+st]; __syncthreads(); }
    if (t == 0) g_d0[row] = red[0];
    __syncthreads();
    red[t] = pd1; __syncthreads();
    for (int st = 64; st > 0; st >>= 1) { if (t < st) red[t] += red[t+st]; __syncthreads(); }
    if (t == 0) g_d1b[row] = red[0];
}

// ---------------- K3: three GEMMs, 1D grid of 384 fully-active CTAs ----------------
// bid [0,192):   op2  XV   = xh @ V_w          (512x384, NN, ldb=384)
// bid [192,288): op0  henc = gelu(z@enc_w+b)   (512x192, NN, ldb=192)
// bid [288,384): op1  w    = z @ dec_w^T       (512x192, NT)
__global__ __launch_bounds__(TPB) void k3_gemm(const float* __restrict__ enc_w,
                                               const float* __restrict__ enc_b,
                                               const float* __restrict__ dec_w,
                                               const float* __restrict__ V_w) {
    __shared__ __align__(16) float As[2][BK][BM+4];
    __shared__ __align__(16) float Bs[2][BK][2*BN+4];
    const int bid = blockIdx.x;
    int op, bx, by;
    if (bid < 192)      { op = 2; bx = bid % 12;        by = bid / 12; }
    else if (bid < 288) { op = 0; int i = bid-192; bx = i % 6; by = i / 6; }
    else                { op = 1; int i = bid-288; bx = i % 6; by = i / 6; }
    const int n0 = bx*BN, m0 = by*BM;

    const int t  = threadIdx.x;
    const int tx = t & 15, ty = t >> 4;
    const int ar = t >> 3, ac = (t & 7) * 4;
    const int bk = t >> 3, bn = (t & 7) * 4;   // NN mapping
    const int nt = t >> 3, kc = (t & 7) * 4;   // NT mapping

    const float* A = (op == 2) ? g_xh : g_z;
    const float* Bp = (op == 0) ? enc_w : V_w;
    const int ldb = (op == 0) ? HID : FEAT;

    ull acc0=0, acc1=0, acc2=0, acc3=0;
    float4 a0v, a1v, b0v, b1v;

    const float* Ar0 = A + (m0+ar)*ZDIM + ac;
    const float* Ar1 = A + (m0+ar+16)*ZDIM + ac;

    // ---- prologue load+store (k-tile 0) ----
    a0v = *(const float4*)(Ar0);
    a1v = *(const float4*)(Ar1);
    if (op != 1) {
        b0v = *(const float4*)(Bp + bk*ldb + n0 + bn);
        b1v = *(const float4*)(Bp + (bk+16)*ldb + n0 + bn);
    } else {
        b0v = *(const float4*)(dec_w + (n0+nt)*ZDIM + kc);
        b1v = *(const float4*)(dec_w + (n0+nt+16)*ZDIM + kc);
    }
    #pragma unroll
    for (int j=0;j<4;j++){ As[0][ac+j][ar]=(&a0v.x)[j]; As[0][ac+j][ar+16]=(&a1v.x)[j]; }
    if (op != 1) {
        *(float4*)&Bs[0][bk   ][bn*2  ] = make_float4(b0v.x,b0v.x,b0v.y,b0v.y);
        *(float4*)&Bs[0][bk   ][bn*2+4] = make_float4(b0v.z,b0v.z,b0v.w,b0v.w);
        *(float4*)&Bs[0][bk+16][bn*2  ] = make_float4(b1v.x,b1v.x,b1v.y,b1v.y);
        *(float4*)&Bs[0][bk+16][bn*2+4] = make_float4(b1v.z,b1v.z,b1v.w,b1v.w);
    } else {
        #pragma unroll
        for (int j=0;j<4;j++){
            *(float2*)&Bs[0][kc+j][2*nt]      = make_float2((&b0v.x)[j],(&b0v.x)[j]);
            *(float2*)&Bs[0][kc+j][2*(nt+16)] = make_float2((&b1v.x)[j],(&b1v.x)[j]);
        }
    }
    __syncthreads();

    int buf = 0;
    #pragma unroll 1
    for (int kt = 0; kt < ZDIM/BK; kt++) {
        if (kt < ZDIM/BK - 1) {
            const int k0 = (kt+1)*BK;
            a0v = *(const float4*)(Ar0 + k0);
            a1v = *(const float4*)(Ar1 + k0);
            if (op != 1) {
                b0v = *(const float4*)(Bp + (k0+bk)*ldb + n0 + bn);
                b1v = *(const float4*)(Bp + (k0+bk+16)*ldb + n0 + bn);
            } else {
                b0v = *(const float4*)(dec_w + (n0+nt)*ZDIM + k0 + kc);
                b1v = *(const float4*)(dec_w + (n0+nt+16)*ZDIM + k0 + kc);
            }
        }
        #pragma unroll
        for (int kk = 0; kk < BK; kk++) {
            ulonglong2 av = *(const ulonglong2*)&As[buf][kk][ty*4];
            ulonglong2 bv = *(const ulonglong2*)&Bs[buf][kk][tx*4];
            fma2(acc0, av.x, bv.x);
            fma2(acc1, av.x, bv.y);
            fma2(acc2, av.y, bv.x);
            fma2(acc3, av.y, bv.y);
        }
        if (kt < ZDIM/BK - 1) {
            const int nb = buf ^ 1;
            #pragma unroll
            for (int j=0;j<4;j++){ As[nb][ac+j][ar]=(&a0v.x)[j]; As[nb][ac+j][ar+16]=(&a1v.x)[j]; }
            if (op != 1) {
                *(float4*)&Bs[nb][bk   ][bn*2  ] = make_float4(b0v.x,b0v.x,b0v.y,b0v.y);
                *(float4*)&Bs[nb][bk   ][bn*2+4] = make_float4(b0v.z,b0v.z,b0v.w,b0v.w);
                *(float4*)&Bs[nb][bk+16][bn*2  ] = make_float4(b1v.x,b1v.x,b1v.y,b1v.y);
                *(float4*)&Bs[nb][bk+16][bn*2+4] = make_float4(b1v.z,b1v.z,b1v.w,b1v.w);
            } else {
                #pragma unroll
                for (int j=0;j<4;j++){
                    *(float2*)&Bs[nb][kc+j][2*nt]      = make_float2((&b0v.x)[j],(&b0v.x)[j]);
                    *(float2*)&Bs[nb][kc+j][2*(nt+16)] = make_float2((&b1v.x)[j],(&b1v.x)[j]);
                }
            }
        }
        __syncthreads();
        buf ^= 1;
    }

    const int col = n0 + tx*2;
    const int r   = m0 + ty*4;
    float2 c0 = unpack2(acc0), c1 = unpack2(acc1), c2 = unpack2(acc2), c3 = unpack2(acc3);
    if (op == 0) {
        float b0 = enc_b[col], b1 = enc_b[col+1];
        g_henc[(r+0)*HID+col  ] = gelu_f(c0.x + b0);
        g_henc[(r+1)*HID+col  ] = gelu_f(c0.y + b0);
        g_henc[(r+2)*HID+col  ] = gelu_f(c2.x + b0);
        g_henc[(r+3)*HID+col  ] = gelu_f(c2.y + b0);
        g_henc[(r+0)*HID+col+1] = gelu_f(c1.x + b1);
        g_henc[(r+1)*HID+col+1] = gelu_f(c1.y + b1);
        g_henc[(r+2)*HID+col+1] = gelu_f(c3.x + b1);
        g_henc[(r+3)*HID+col+1] = gelu_f(c3.y + b1);
    } else if (op == 1) {
        g_w[(r+0)*HID+col  ] = c0.x;  g_w[(r+1)*HID+col  ] = c0.y;
        g_w[(r+2)*HID+col  ] = c2.x;  g_w[(r+3)*HID+col  ] = c2.y;
        g_w[(r+0)*HID+col+1] = c1.x;  g_w[(r+1)*HID+col+1] = c1.y;
        g_w[(r+2)*HID+col+1] = c3.x;  g_w[(r+3)*HID+col+1] = c3.y;
    } else {
        g_XV[(r+0)*FEAT+col  ] = c0.x;  g_XV[(r+1)*FEAT+col  ] = c0.y;
        g_XV[(r+2)*FEAT+col  ] = c2.x;  g_XV[(r+3)*FEAT+col  ] = c2.y;
        g_XV[(r+0)*FEAT+col+1] = c1.x;  g_XV[(r+1)*FEAT+col+1] = c1.y;
        g_XV[(r+2)*FEAT+col+1] = c3.x;  g_XV[(r+3)*FEAT+col+1] = c3.y;
    }
}

// ---------------- K4: per batch — d1, softmax collapse, alpha/beta, T ----------------
__global__ __launch_bounds__(384) void k4_batch() {
    const int b = blockIdx.x;
    const int t = threadIdx.x;
    __shared__ float sd0[128], sd1[128], sE0[128], red[128];

    if (t < 128) sd0[t] = g_d0[b*128 + t];

    const int wid = t >> 5, lane = t & 31;
    for (int i = wid; i < 128; i += 12) {
        int g = b*128 + i;
        float acc = 0.f;
        #pragma unroll
        for (int j = 0; j < 6; j++) {
            int h = lane + j*32;
            acc += g_henc[g*HID + h] * g_w[g*HID + h];
        }
        #pragma unroll
        for (int o = 16; o; o >>= 1) acc += __shfl_xor_sync(0xffffffffu, acc, o);
        if (lane == 0) sd1[i] = acc + g_d1b[g];
    }
    __syncthreads();

    if (t < 128) red[t] = fmaxf(sd0[t], sd1[t]);
    __syncthreads();
    for (int st = 64; st > 0; st >>= 1) { if (t < st) red[t] = fmaxf(red[t], red[t+st]); __syncthreads(); }
    float M = red[0];
    __syncthreads();

    float e0 = 0.f, e1 = 0.f;
    if (t < 128) {
        e0 = expf(sd0[t] - M);
        e1 = expf(sd1[t] - M);
        sE0[t] = e0;
        red[t] = e0;
    }
    __syncthreads();
    for (int st = 64; st > 0; st >>= 1) { if (t < st) red[t] += red[t+st]; __syncthreads(); }
    float Ssum = red[0];

    if (t < 128) {
        float S = Ssum - e0 + e1;
        float a = 1.0f / S;
        g_alpha[b*128 + t] = a;
        g_beta [b*128 + t] = (e1 - e0) * a;
    }

    // T[f] = sum_j E0[j] * xh[b,j,f]
    float acc = 0.f;
    #pragma unroll 4
    for (int j = 0; j < 128; j++) acc += sE0[j] * g_xh[(b*128 + j)*ZDIM + t];
    g_T[b*ZDIM + t] = acc;
}

// ---------------- K4b: TV[b] = T[b] @ V_w  (grid 4x3, 128 thr) ----------------
__global__ __launch_bounds__(128) void k4b_tv(const float* __restrict__ V_w) {
    const int b = blockIdx.x;
    const int t = threadIdx.x;
    const int f = blockIdx.y * 128 + t;
    __shared__ float sT[ZDIM];
    sT[t] = g_T[b*ZDIM + t];
    sT[t+128] = g_T[b*ZDIM + t + 128];
    sT[t+256] = g_T[b*ZDIM + t + 256];
    __syncthreads();
    float acc = 0.f;
    #pragma unroll 8
    for (int k = 0; k < ZDIM; k++) acc += sT[k] * V_w[k*FEAT + f];
    g_TV[b*FEAT + f] = acc;
}

// ---------------- K5: y = alpha*TV + beta*XV + V_b ----------------
__global__ __launch_bounds__(384) void k5_out(const float* __restrict__ V_b,
                                              float* __restrict__ out) {
    const int m = blockIdx.x;
    const int t = threadIdx.x;
    const int b = m >> 7;
    out[m*FEAT + t] = g_alpha[m] * g_TV[b*FEAT + t]
                    + g_beta[m]  * g_XV[m*FEAT + t]
                    + V_b[t];
}

// ---------------- launch ----------------
extern "C" void kernel_launch(void* const* d_in, const int* in_sizes, int n_in,
                              void* d_out, int out_size) {
    const float* x     = (const float*)d_in[0];
    const float* U_w   = (const float*)d_in[1];
    const float* U_b   = (const float*)d_in[2];
    const float* ln_w  = (const float*)d_in[3];
    const float* ln_b  = (const float*)d_in[4];
    const float* enc_w = (const float*)d_in[5];
    const float* enc_b = (const float*)d_in[6];
    const float* dec_w = (const float*)d_in[7];
    const float* dec_b = (const float*)d_in[8];
    const float* V_w   = (const float*)d_in[9];
    const float* V_b   = (const float*)d_in[10];
    float* out = (float*)d_out;

    k0_c0<<<1, 384>>>(enc_b, dec_w, dec_b);
    k1_gemm<<<384, TPB>>>(x, U_w, U_b);
    k2_ln<<<ROWS, 128>>>(ln_w, ln_b, dec_b);
    k3_gemm<<<384, TPB>>>(enc_w, enc_b, dec_w, V_w);
    k4_batch<<<BB, 384>>>();
    k4b_tv<<<dim3(BB, 3), 128>>>(V_w);
    k5_out<<<ROWS, 384>>>(V_b, out);
}